// round 15
// baseline (speedup 1.0000x reference)
#include <cuda_runtime.h>

#define TPB    256
#define DIM    4096
#define KSEL   409
#define NWARP  (TPB / 32)
#define MAXC   512
#define NCTAS  1184        // 148 SMs x 8 persistent CTA slots

// 256 exact power-of-two bins over (1.5, 2.0]: bin = (|x|-1.5)*512 via
// fma(|x|,512,-768), EXACT for |x| in (1.5,2) -> deterministic membership.
// >=2.0 saturates into overflow bin 255; top-down cumulative == count(|x| >= edge).
// Rank bin not found below 255 -> generic bisection fallback (exact, any data).
//
// PERSISTENT CTAs + software pipeline: each CTA loops over rows; the next row's
// 16 LDG.128 values are prefetched into registers right after the current row's
// values are consumed (STS+hist), so DRAM streams continuously while the
// barrier-serialized scan/gather/select/epilogue chain runs. Row smem buffer
// needs no extra barrier: every thread re-reads only the words it wrote.
__global__ __launch_bounds__(TPB) void sparsify_kernel(const float* __restrict__ x,
                                                       float* __restrict__ out,
                                                       int rows) {
    __shared__ float    s_row[DIM];            // 16 KB staged current row
    __shared__ int      s_hist[256];
    __shared__ unsigned s_w[NWARP];
    __shared__ float    s_wf[NWARP];
    __shared__ float    s_memb[MAXC];
    __shared__ int      s_cnt;
    __shared__ int      s_selbin, s_need;
    __shared__ float    s_thr;

    const int t    = threadIdx.x;
    const int lane = t & 31;
    const int wid  = t >> 5;

    float4* srow4 = reinterpret_cast<float4*>(s_row);

    s_hist[t] = 0;
    if (t == 0) { s_cnt = 0; s_selbin = 255; s_need = 1; s_thr = 1.645f; }

    // ---- prologue: prefetch first row into registers ----
    int r = blockIdx.x;
    float4 v0, v1, v2, v3;
    {
        const float4* xr = reinterpret_cast<const float4*>(x + (size_t)r * DIM);
        v0 = __ldcs(&xr[t]);           v1 = __ldcs(&xr[t + TPB]);
        v2 = __ldcs(&xr[t + 2 * TPB]); v3 = __ldcs(&xr[t + 3 * TPB]);
    }
    __syncthreads();                                   // B1 (once)

    for (; r < rows; r += NCTAS) {
        // ---- step 1: stage regs -> smem, exact histogram, candidate mask ----
        srow4[t]           = v0;
        srow4[t + TPB]     = v1;
        srow4[t + 2 * TPB] = v2;
        srow4[t + 3 * TPB] = v3;
        unsigned cmask = 0;
        #define HC(e, i) { float d = fmaf(fabsf(e), 512.0f, -768.0f); \
                           if (d > 0.0f) { \
                               int b = min(__float2int_rz(d), 255); \
                               atomicAdd(&s_hist[b], 1); \
                               cmask |= 1u << (i); } }
        HC(v0.x, 0)  HC(v0.y, 1)  HC(v0.z, 2)  HC(v0.w, 3)
        HC(v1.x, 4)  HC(v1.y, 5)  HC(v1.z, 6)  HC(v1.w, 7)
        HC(v2.x, 8)  HC(v2.y, 9)  HC(v2.z, 10) HC(v2.w, 11)
        HC(v3.x, 12) HC(v3.y, 13) HC(v3.z, 14) HC(v3.w, 15)
        #undef HC
        __syncthreads();                               // B2

        // ---- prefetch NEXT row into registers (overlaps scan..epilogue) ----
        {
            int rn = r + NCTAS;
            if (rn < rows) {
                const float4* xn = reinterpret_cast<const float4*>(x + (size_t)rn * DIM);
                v0 = __ldcs(&xn[t]);           v1 = __ldcs(&xn[t + TPB]);
                v2 = __ldcs(&xn[t + 2 * TPB]); v3 = __ldcs(&xn[t + 3 * TPB]);
            }
        }

        // ---- warp 0: top-down scan of 256 bins -> rank bin + local rank ----
        if (wid == 0) {
            const int base = 255 - 8 * lane;           // lane0: bins 255..248, ...
            int h[8]; int lsum = 0;
            #pragma unroll
            for (int k = 0; k < 8; k++) { h[k] = s_hist[base - k]; lsum += h[k]; }
            int cum = lsum;
            #pragma unroll
            for (int o = 1; o < 32; o <<= 1) {
                int n = __shfl_up_sync(0xFFFFFFFFu, cum, o);
                if (lane >= o) cum += n;
            }
            unsigned bal = __ballot_sync(0xFFFFFFFFu, cum >= KSEL);
            if (bal) {
                int L = __ffs(bal) - 1;
                if (lane == L) {
                    int ca = cum - lsum;               // count strictly above lane's bins
                    int sel = 255, rr = 1;
                    #pragma unroll
                    for (int k = 0; k < 8; k++) {
                        if (ca + h[k] >= KSEL) { sel = base - k; rr = KSEL - ca; break; }
                        ca += h[k];
                    }
                    s_selbin = sel; s_need = rr;
                }
            }
            // bal == 0 -> s_selbin stays 255 -> fallback
        }
        __syncthreads();                               // B3

        const int sb = s_selbin;                       // uniform across CTA
        int nd;
        if (sb < 255) {
            // ---- sparse gather from smem row: only groups holding candidates ----
            nd = s_need;
            #pragma unroll
            for (int u = 0; u < 4; u++) {
                unsigned g = (cmask >> (4 * u)) & 0xFu;
                if (g) {
                    float4 v = srow4[t + u * TPB];
                    #define TG(e, i) if (g & (1u << (i))) { \
                            float d = fmaf(fabsf(e), 512.0f, -768.0f); \
                            if (__float2int_rz(d) == sb) { \
                                int id = atomicAdd(&s_cnt, 1); \
                                if (id < MAXC) s_memb[id] = fabsf(e); } }
                    TG(v.x, 0) TG(v.y, 1) TG(v.z, 2) TG(v.w, 3)
                    #undef TG
                }
            }
        } else {
            // ---- generic fallback: exact bisection over smem row (~never) ----
            float m = 0.0f;
            #pragma unroll
            for (int u = 0; u < 4; u++) {
                float4 v = srow4[t + u * TPB];
                m = fmaxf(m, fmaxf(fmaxf(fabsf(v.x), fabsf(v.y)),
                                   fmaxf(fabsf(v.z), fabsf(v.w))));
            }
            #pragma unroll
            for (int o = 16; o; o >>= 1) m = fmaxf(m, __shfl_xor_sync(0xFFFFFFFFu, m, o));
            if (lane == 0) s_wf[wid] = m;
            __syncthreads();
            float maxv = s_wf[0];
            #pragma unroll
            for (int w = 1; w < NWARP; w++) maxv = fmaxf(maxv, s_wf[w]);
            __syncthreads();

            float lo = -1.0f, hi = maxv;
            int cLo = DIM, cHi = 0, guard = 0;
            while ((cLo - cHi) > (MAXC - 64) && guard < 40) {
                float mid = 0.5f * (lo + hi);
                if (!(mid > lo && mid < hi)) break;    // degenerate (ties)
                int cc = 0;
                #pragma unroll
                for (int u = 0; u < 4; u++) {
                    float4 v = srow4[t + u * TPB];
                    cc += fabsf(v.x) > mid; cc += fabsf(v.y) > mid;
                    cc += fabsf(v.z) > mid; cc += fabsf(v.w) > mid;
                }
                unsigned rr = __reduce_add_sync(0xFFFFFFFFu, (unsigned)cc);
                if (lane == 0) s_w[wid] = rr;
                __syncthreads();
                unsigned tot = 0;
                #pragma unroll
                for (int w = 0; w < NWARP; w++) tot += s_w[w];
                __syncthreads();
                if ((int)tot >= KSEL) { lo = mid; cLo = (int)tot; }
                else                  { hi = mid; cHi = (int)tot; }
                guard++;
            }
            if (t == 0) s_cnt = 0;
            __syncthreads();
            #pragma unroll
            for (int u = 0; u < 4; u++) {
                float4 v = srow4[t + u * TPB];
                #define TG2(e) { float av = fabsf(e); \
                                 if (av > lo && av <= hi) { int id = atomicAdd(&s_cnt, 1); \
                                     if (id < MAXC) s_memb[id] = av; } }
                TG2(v.x) TG2(v.y) TG2(v.z) TG2(v.w)
                #undef TG2
            }
            nd = KSEL - cHi;
        }
        s_hist[t] = 0;                                 // re-zero for next row (pre-B4)
        __syncthreads();                               // B4

        // ---- exact select: nd-th largest among c members (typically c ~ 2-4) ----
        const int c = min(s_cnt, MAXC);
        for (int j = t; j < c; j += TPB) {
            float vj = s_memb[j];
            int gt = 0, ge = 0;
            for (int i = 0; i < c; i++) {
                float vi = s_memb[i];
                gt += vi > vj;
                ge += vi >= vj;
            }
            if (gt < nd && nd <= ge) s_thr = vj;       // matching writers write same value
        }
        if (t == 0) { s_cnt = 0; s_selbin = 255; s_need = 1; }   // reset for next row
        __syncthreads();                               // B5

        const float thr   = s_thr;
        const float bias5 = -5.0f * thr;

        // ---- epilogue: re-read OWN smem words, out = x*(0.5+0.5*tanh(5(|x|-thr))) ----
        float4* orow = reinterpret_cast<float4*>(out + (size_t)r * DIM);
        #pragma unroll
        for (int u = 0; u < 4; u++) {
            float4 v = srow4[t + u * TPB];
            float4 o;
            #define MK(dst, xv) { float z = fmaf(5.0f, fabsf(xv), bias5); float th; \
                                  asm("tanh.approx.f32 %0, %1;" : "=f"(th) : "f"(z)); \
                                  dst = (xv) * fmaf(0.5f, th, 0.5f); }
            MK(o.x, v.x) MK(o.y, v.y) MK(o.z, v.z) MK(o.w, v.w)
            #undef MK
            __stcs(&orow[t + u * TPB], o);
        }
        // no barrier needed: next iteration's STS writes each thread's own words
    }
}

extern "C" void kernel_launch(void* const* d_in, const int* in_sizes, int n_in,
                              void* d_out, int out_size) {
    const float* x = (const float*)d_in[0];
    float* out = (float*)d_out;
    const int rows = in_sizes[0] / DIM;   // 4 * 2048 = 8192 rows
    sparsify_kernel<<<NCTAS, TPB>>>(x, out, rows);
}

// round 17
// speedup vs baseline: 1.1460x; 1.1460x over previous
#include <cuda_runtime.h>
#include <cstdint>

#define TPB    256
#define DIM    4096
#define KSEL   409
#define NWARP  (TPB / 32)
#define MAXC   512
#define NCTAS  888          // 148 SMs x 6 resident CTAs (smem-limited)

// 256 exact power-of-two bins over (1.5, 2.0]: bin = (|x|-1.5)*512 via
// fma(|x|,512,-768), EXACT for |x| in (1.5,2) -> deterministic membership.
// >=2.0 saturates into overflow bin 255; top-down cumulative == count(|x| >= edge).
// Rank bin not found below 255 -> generic bisection fallback (exact, any data).
//
// PERSISTENT CTAs + cp.async double-buffered smem rows: the next row streams
// gmem->smem via LDGSTS (no registers held) while the current row walks the
// barrier-serialized scan/gather/select/epilogue chain. The row buffer is
// thread-private (thread t only touches words t+u*TPB, and fills them with its
// own cp.async), so buffer handoff needs only cp.async.wait_group -- no extra
// barriers (4 barriers/row total).
__global__ __launch_bounds__(TPB, 6) void sparsify_kernel(const float* __restrict__ x,
                                                          float* __restrict__ out,
                                                          int rows) {
    __shared__ float    s_buf[2][DIM];         // 32 KB double-buffered rows
    __shared__ int      s_hist[256];
    __shared__ unsigned s_w[NWARP];
    __shared__ float    s_wf[NWARP];
    __shared__ float    s_memb[MAXC];
    __shared__ int      s_cnt;
    __shared__ int      s_selbin, s_need;
    __shared__ float    s_thr;

    const int t    = threadIdx.x;
    const int lane = t & 31;
    const int wid  = t >> 5;

    // this thread's four float4 slots (same ownership in both buffers)
    const unsigned int sb0 =
        (unsigned int)__cvta_generic_to_shared(&s_buf[0][0]) + (unsigned int)t * 16u;
    const unsigned int sb1 =
        (unsigned int)__cvta_generic_to_shared(&s_buf[1][0]) + (unsigned int)t * 16u;

    s_hist[t] = 0;
    if (t == 0) { s_cnt = 0; s_selbin = 255; s_need = 1; s_thr = 1.645f; }

    // ---- prologue: async-prefetch first row into buffer 0 ----
    int r = blockIdx.x;
    {
        const float4* xr = reinterpret_cast<const float4*>(x + (size_t)r * DIM);
        #pragma unroll
        for (int u = 0; u < 4; u++)
            asm volatile("cp.async.cg.shared.global [%0], [%1], 16;"
                         :: "r"(sb0 + u * (TPB * 16)), "l"(xr + t + u * TPB));
        asm volatile("cp.async.commit_group;");
    }
    __syncthreads();                                   // B1 (once; orders hist init)

    int cur = 0;
    for (; r < rows; r += NCTAS, cur ^= 1) {
        const unsigned int sbn = cur ? sb0 : sb1;
        float4* srow4 = reinterpret_cast<float4*>(&s_buf[cur][0]);

        // wait for this row's async copies (per-thread; own words only)
        asm volatile("cp.async.wait_group 0;");

        // ---- step 1: exact histogram + candidate mask over own smem words ----
        unsigned cmask = 0;
        #pragma unroll
        for (int u = 0; u < 4; u++) {
            float4 v = srow4[t + u * TPB];
            #define HC(e, i) { float d = fmaf(fabsf(e), 512.0f, -768.0f); \
                               if (d > 0.0f) { \
                                   int b = min(__float2int_rz(d), 255); \
                                   atomicAdd(&s_hist[b], 1); \
                                   cmask |= 1u << (4 * u + (i)); } }
            HC(v.x, 0) HC(v.y, 1) HC(v.z, 2) HC(v.w, 3)
            #undef HC
        }

        // ---- issue prefetch of NEXT row (overlaps scan..epilogue) ----
        {
            int rn = r + NCTAS;
            if (rn < rows) {
                const float4* xn = reinterpret_cast<const float4*>(x + (size_t)rn * DIM);
                #pragma unroll
                for (int u = 0; u < 4; u++)
                    asm volatile("cp.async.cg.shared.global [%0], [%1], 16;"
                                 :: "r"(sbn + u * (TPB * 16)), "l"(xn + t + u * TPB));
            }
            asm volatile("cp.async.commit_group;");
        }
        __syncthreads();                               // B2 (hist complete)

        // ---- warp 0: top-down scan of 256 bins -> rank bin + local rank ----
        if (wid == 0) {
            const int base = 255 - 8 * lane;           // lane0: bins 255..248, ...
            int h[8]; int lsum = 0;
            #pragma unroll
            for (int k = 0; k < 8; k++) { h[k] = s_hist[base - k]; lsum += h[k]; }
            int cum = lsum;
            #pragma unroll
            for (int o = 1; o < 32; o <<= 1) {
                int n = __shfl_up_sync(0xFFFFFFFFu, cum, o);
                if (lane >= o) cum += n;
            }
            unsigned bal = __ballot_sync(0xFFFFFFFFu, cum >= KSEL);
            if (bal) {
                int L = __ffs(bal) - 1;
                if (lane == L) {
                    int ca = cum - lsum;               // count strictly above lane's bins
                    int sel = 255, rr = 1;
                    #pragma unroll
                    for (int k = 0; k < 8; k++) {
                        if (ca + h[k] >= KSEL) { sel = base - k; rr = KSEL - ca; break; }
                        ca += h[k];
                    }
                    s_selbin = sel; s_need = rr;
                }
            }
            // bal == 0 -> s_selbin stays 255 -> fallback
        }
        __syncthreads();                               // B3

        const int sb = s_selbin;                       // uniform across CTA
        int nd;
        if (sb < 255) {
            // ---- sparse gather: only own float4 groups holding candidates ----
            nd = s_need;
            #pragma unroll
            for (int u = 0; u < 4; u++) {
                unsigned g = (cmask >> (4 * u)) & 0xFu;
                if (g) {
                    float4 v = srow4[t + u * TPB];
                    #define TG(e, i) if (g & (1u << (i))) { \
                            float d = fmaf(fabsf(e), 512.0f, -768.0f); \
                            if (__float2int_rz(d) == sb) { \
                                int id = atomicAdd(&s_cnt, 1); \
                                if (id < MAXC) s_memb[id] = fabsf(e); } }
                    TG(v.x, 0) TG(v.y, 1) TG(v.z, 2) TG(v.w, 3)
                    #undef TG
                }
            }
        } else {
            // ---- generic fallback: exact bisection over own smem words (~never) ----
            float m = 0.0f;
            #pragma unroll
            for (int u = 0; u < 4; u++) {
                float4 v = srow4[t + u * TPB];
                m = fmaxf(m, fmaxf(fmaxf(fabsf(v.x), fabsf(v.y)),
                                   fmaxf(fabsf(v.z), fabsf(v.w))));
            }
            #pragma unroll
            for (int o = 16; o; o >>= 1) m = fmaxf(m, __shfl_xor_sync(0xFFFFFFFFu, m, o));
            if (lane == 0) s_wf[wid] = m;
            __syncthreads();
            float maxv = s_wf[0];
            #pragma unroll
            for (int w = 1; w < NWARP; w++) maxv = fmaxf(maxv, s_wf[w]);
            __syncthreads();

            float lo = -1.0f, hi = maxv;
            int cLo = DIM, cHi = 0, guard = 0;
            while ((cLo - cHi) > (MAXC - 64) && guard < 40) {
                float mid = 0.5f * (lo + hi);
                if (!(mid > lo && mid < hi)) break;    // degenerate (ties)
                int cc = 0;
                #pragma unroll
                for (int u = 0; u < 4; u++) {
                    float4 v = srow4[t + u * TPB];
                    cc += fabsf(v.x) > mid; cc += fabsf(v.y) > mid;
                    cc += fabsf(v.z) > mid; cc += fabsf(v.w) > mid;
                }
                unsigned rr = __reduce_add_sync(0xFFFFFFFFu, (unsigned)cc);
                if (lane == 0) s_w[wid] = rr;
                __syncthreads();
                unsigned tot = 0;
                #pragma unroll
                for (int w = 0; w < NWARP; w++) tot += s_w[w];
                __syncthreads();
                if ((int)tot >= KSEL) { lo = mid; cLo = (int)tot; }
                else                  { hi = mid; cHi = (int)tot; }
                guard++;
            }
            if (t == 0) s_cnt = 0;
            __syncthreads();
            #pragma unroll
            for (int u = 0; u < 4; u++) {
                float4 v = srow4[t + u * TPB];
                #define TG2(e) { float av = fabsf(e); \
                                 if (av > lo && av <= hi) { int id = atomicAdd(&s_cnt, 1); \
                                     if (id < MAXC) s_memb[id] = av; } }
                TG2(v.x) TG2(v.y) TG2(v.z) TG2(v.w)
                #undef TG2
            }
            nd = KSEL - cHi;
        }
        s_hist[t] = 0;                                 // re-zero for next row (post-scan)
        __syncthreads();                               // B4

        // ---- exact select: nd-th largest among c members (typically c ~ 2-4) ----
        const int c = min(s_cnt, MAXC);
        for (int j = t; j < c; j += TPB) {
            float vj = s_memb[j];
            int gt = 0, ge = 0;
            for (int i = 0; i < c; i++) {
                float vi = s_memb[i];
                gt += vi > vj;
                ge += vi >= vj;
            }
            if (gt < nd && nd <= ge) s_thr = vj;       // matching writers write same value
        }
        if (t == 0) { s_cnt = 0; s_selbin = 255; s_need = 1; }   // reset for next row
        __syncthreads();                               // B5

        const float thr   = s_thr;
        const float bias5 = -5.0f * thr;

        // ---- epilogue: own smem words, out = x*(0.5+0.5*tanh(5(|x|-thr))) ----
        float4* orow = reinterpret_cast<float4*>(out + (size_t)r * DIM);
        #pragma unroll
        for (int u = 0; u < 4; u++) {
            float4 v = srow4[t + u * TPB];
            float4 o;
            #define MK(dst, xv) { float z = fmaf(5.0f, fabsf(xv), bias5); float th; \
                                  asm("tanh.approx.f32 %0, %1;" : "=f"(th) : "f"(z)); \
                                  dst = (xv) * fmaf(0.5f, th, 0.5f); }
            MK(o.x, v.x) MK(o.y, v.y) MK(o.z, v.z) MK(o.w, v.w)
            #undef MK
            __stcs(&orow[t + u * TPB], o);
        }
        // no barrier: next iteration touches the OTHER buffer; this buffer's
        // refill (issued next iteration) is by this same thread, own words only
    }
}

extern "C" void kernel_launch(void* const* d_in, const int* in_sizes, int n_in,
                              void* d_out, int out_size) {
    const float* x = (const float*)d_in[0];
    float* out = (float*)d_out;
    const int rows = in_sizes[0] / DIM;   // 4 * 2048 = 8192 rows
    sparsify_kernel<<<NCTAS, TPB>>>(x, out, rows);
}